// round 7
// baseline (speedup 1.0000x reference)
#include <cuda_runtime.h>
#include <cuda_bf16.h>

#define NQ    18
#define NBAT  16

typedef unsigned long long u64;

// ---- f32x2 packed helpers ----
__device__ __forceinline__ u64 pk(float lo, float hi) {
    u64 r; asm("mov.b64 %0,{%1,%2};" : "=l"(r) : "f"(lo), "f"(hi)); return r;
}
__device__ __forceinline__ void upk(u64 v, float& lo, float& hi) {
    asm("mov.b64 {%0,%1},%2;" : "=f"(lo), "=f"(hi) : "l"(v));
}
__device__ __forceinline__ u64 fma2(u64 a, u64 b, u64 c) {
    u64 d; asm("fma.rn.f32x2 %0,%1,%2,%3;" : "=l"(d) : "l"(a), "l"(b), "l"(c)); return d;
}
__device__ __forceinline__ u64 mul2(u64 a, u64 b) {
    u64 d; asm("mul.rn.f32x2 %0,%1,%2;" : "=l"(d) : "l"(a), "l"(b)); return d;
}
__device__ __forceinline__ u64 add2(u64 a, u64 b) {
    u64 d; asm("add.rn.f32x2 %0,%1,%2;" : "=l"(d) : "l"(a), "l"(b)); return d;
}

// Bond state s=(w<<2)|(y<<1)|y' packed as pairs P[p]=(2p,2p+1).
// Forward site op F = C*B*A, backward (transpose) G = B*A*C — verified R2-R5.

__shared__ u64   g_cst[NQ][NBAT][5];   // per-site packed coefficients
__shared__ u64   g_L[9][NBAT][5];      // L_0..L_8
__shared__ u64   g_S[NQ][NBAT][5];     // S_8..S_17 (indexed by site)
__shared__ float g_tf[9][NBAT][8];     // fwd rank terms for i=9..17
__shared__ float g_tb[8][NBAT][8];     // bwd rank terms for k=0..7

__device__ __forceinline__ void site_fwd(int i, int b, u64& P0, u64& P1, u64& P2, u64& P3) {
    const u64 r0e = g_cst[i][b][1], r0o = g_cst[i][b][2];
    const u64 r1e = g_cst[i][b][3], r1o = g_cst[i][b][4];
    float C0, S0; upk(g_cst[i][b][0], C0, S0);
    const u64 C0p = pk(C0, C0), S0p = pk(S0, S0);
    const u64 T0 = fma2(C0p, P0, mul2(S0p, P1));
    const u64 T1 = fma2(C0p, P1, mul2(S0p, P0));
    const u64 T2 = fma2(C0p, P2, mul2(S0p, P3));
    const u64 T3 = fma2(C0p, P3, mul2(S0p, P2));
    float t0,t1,t2,t3,t4,t5,t6,t7;
    upk(T0,t0,t1); upk(T1,t2,t3); upk(T2,t4,t5); upk(T3,t6,t7);
    const u64 V0 = pk(fmaf(C0,t0,S0*t1), fmaf(C0,t1,S0*t0));
    const u64 V1 = pk(fmaf(C0,t2,S0*t3), fmaf(C0,t3,S0*t2));
    const u64 V2 = pk(fmaf(C0,t4,S0*t5), fmaf(C0,t5,S0*t4));
    const u64 V3 = pk(fmaf(C0,t6,S0*t7), fmaf(C0,t7,S0*t6));
    P0 = fma2(r0e, V0, mul2(r1e, V2));
    P1 = fma2(r0o, V1, mul2(r1o, V3));
    P2 = fma2(r0e, V2, mul2(r1e, V0));
    P3 = fma2(r0o, V3, mul2(r1o, V1));
}

__device__ __forceinline__ void site_bwd(int i, int b, u64& U0, u64& U1, u64& U2, u64& U3) {
    const u64 r0e = g_cst[i][b][1], r0o = g_cst[i][b][2];
    const u64 r1e = g_cst[i][b][3], r1o = g_cst[i][b][4];
    float C0, S0; upk(g_cst[i][b][0], C0, S0);
    const u64 C0p = pk(C0, C0), S0p = pk(S0, S0);
    const u64 T0 = fma2(r0e, U0, mul2(r1e, U2));
    const u64 T1 = fma2(r0o, U1, mul2(r1o, U3));
    const u64 T2 = fma2(r0e, U2, mul2(r1e, U0));
    const u64 T3 = fma2(r0o, U3, mul2(r1o, U1));
    const u64 W0 = fma2(C0p, T0, mul2(S0p, T1));
    const u64 W1 = fma2(C0p, T1, mul2(S0p, T0));
    const u64 W2 = fma2(C0p, T2, mul2(S0p, T3));
    const u64 W3 = fma2(C0p, T3, mul2(S0p, T2));
    float w0,w1,w2,w3,w4,w5,w6,w7;
    upk(W0,w0,w1); upk(W1,w2,w3); upk(W2,w4,w5); upk(W3,w6,w7);
    U0 = pk(fmaf(C0,w0,S0*w1), fmaf(C0,w1,S0*w0));
    U1 = pk(fmaf(C0,w2,S0*w3), fmaf(C0,w3,S0*w2));
    U2 = pk(fmaf(C0,w4,S0*w5), fmaf(C0,w5,S0*w4));
    U3 = pk(fmaf(C0,w6,S0*w7), fmaf(C0,w7,S0*w6));
}

// hsum with +/- sign pattern (+ + - -) over the 4 pairs of m = x*y
__device__ __forceinline__ float signed_dot(u64 x0, u64 x1, u64 x2, u64 x3,
                                            u64 y0, u64 y1, u64 y2, u64 y3) {
    const u64 Ap = add2(mul2(x0, y0), mul2(x1, y1));
    const u64 An = add2(mul2(x2, y2), mul2(x3, y3));
    float pl, ph, nl, nh; upk(Ap, pl, ph); upk(An, nl, nh);
    return (pl + ph) - (nl + nh);
}

__global__ void __launch_bounds__(320, 1)
quantum_mps_kernel(const float* __restrict__ in, float* __restrict__ out) {
    const int tid = threadIdx.x;
    const int wid = tid >> 5;
    const int lane = tid & 31;

    // ---- phase 1: coefficient production, 288 threads, one (site,batch) each
    if (tid < 288) {
        const int b = tid / 18, s = tid % 18;
        float c0, sn0, c1, sn1;
        __sincosf(0.5f * in[b * 36 + s],      &sn0, &c0);
        __sincosf(0.5f * in[b * 36 + 18 + s], &sn1, &c1);
        const float cc = c1 * c1, ss = sn1 * sn1, cs = c1 * sn1, ncs = -cs;
        g_cst[s][b][0] = pk(c0,  sn0);
        g_cst[s][b][1] = pk(cc,  ncs);
        g_cst[s][b][2] = pk(ncs, ss);
        g_cst[s][b][3] = pk(ss,  cs);
        g_cst[s][b][4] = pk(cs,  cc);
    }
    __syncthreads();

    // register snapshot storage for matrix-column lanes (disjoint use)
    u64 snap[9][4];

    // ---- phase 2: four concurrent 9-step half-chains
    if (wid == 0) {                       // forward vector: L_0..L_8
        if (lane < NBAT) {
            const int b = lane;
            u64 P0 = pk(1.f, 0.f), P1 = pk(0.f, 0.f), P2 = P1, P3 = P1;
            #pragma unroll
            for (int i = 0; i <= 8; i++) {
                site_fwd(i, b, P0, P1, P2, P3);
                g_L[i][b][0] = P0; g_L[i][b][1] = P1;
                g_L[i][b][2] = P2; g_L[i][b][3] = P3;
            }
        }
    } else if (wid == 1) {                // backward vector: S_17 (=1), S_16..S_8
        if (lane < NBAT) {
            const int b = lane;
            u64 U0 = pk(1.f, 1.f), U1 = U0, U2 = U0, U3 = U0;
            g_S[17][b][0] = U0; g_S[17][b][1] = U1;
            g_S[17][b][2] = U2; g_S[17][b][3] = U3;
            #pragma unroll
            for (int i = 17; i >= 9; i--) {
                site_bwd(i, b, U0, U1, U2, U3);
                g_S[i - 1][b][0] = U0; g_S[i - 1][b][1] = U1;
                g_S[i - 1][b][2] = U2; g_S[i - 1][b][3] = U3;
            }
        }
    } else if (wid < 6) {                 // forward matrix columns X_i = F_i..F_9
        const int g = tid - 64, b = g >> 3, j = g & 7;
        u64 P0 = pk(j == 0 ? 1.f : 0.f, j == 1 ? 1.f : 0.f);
        u64 P1 = pk(j == 2 ? 1.f : 0.f, j == 3 ? 1.f : 0.f);
        u64 P2 = pk(j == 4 ? 1.f : 0.f, j == 5 ? 1.f : 0.f);
        u64 P3 = pk(j == 6 ? 1.f : 0.f, j == 7 ? 1.f : 0.f);
        #pragma unroll
        for (int t = 0; t < 9; t++) {
            site_fwd(9 + t, b, P0, P1, P2, P3);
            snap[t][0] = P0; snap[t][1] = P1; snap[t][2] = P2; snap[t][3] = P3;
        }
    } else {                              // backward matrix columns Y_k = G_{k+1}..G_8
        const int g = tid - 192, b = g >> 3, j = g & 7;
        u64 U0 = pk(j == 0 ? 1.f : 0.f, j == 1 ? 1.f : 0.f);
        u64 U1 = pk(j == 2 ? 1.f : 0.f, j == 3 ? 1.f : 0.f);
        u64 U2 = pk(j == 4 ? 1.f : 0.f, j == 5 ? 1.f : 0.f);
        u64 U3 = pk(j == 6 ? 1.f : 0.f, j == 7 ? 1.f : 0.f);
        #pragma unroll
        for (int t = 0; t < 8; t++) {     // i = 8-t, snapshot = Y_{7-t}
            site_bwd(8 - t, b, U0, U1, U2, U3);
            snap[t][0] = U0; snap[t][1] = U1; snap[t][2] = U2; snap[t][3] = U3;
        }
    }
    __syncthreads();

    // ---- phase 3: rank-term combine on matrix lanes
    if (wid >= 2 && wid < 6) {            // Z_i (i>=9): term = L8[j] * (D.x_j . S_i)
        const int g = tid - 64, b = g >> 3, j = g & 7;
        float e0, e1; upk(g_L[8][b][j >> 1], e0, e1);
        const float L8j = (j & 1) ? e1 : e0;
        #pragma unroll
        for (int t = 0; t < 9; t++) {
            const int i = 9 + t;
            const float q = signed_dot(snap[t][0], snap[t][1], snap[t][2], snap[t][3],
                                       g_S[i][b][0], g_S[i][b][1], g_S[i][b][2], g_S[i][b][3]);
            g_tf[t][b][j] = L8j * q;
        }
    } else if (wid >= 6) {                // Z_k (k<=7): term = S8[j] * (D.y_j . L_k)
        const int g = tid - 192, b = g >> 3, j = g & 7;
        float e0, e1; upk(g_S[8][b][j >> 1], e0, e1);
        const float S8j = (j & 1) ? e1 : e0;
        #pragma unroll
        for (int t = 0; t < 8; t++) {
            const int k = 7 - t;
            const float q = signed_dot(snap[t][0], snap[t][1], snap[t][2], snap[t][3],
                                       g_L[k][b][0], g_L[k][b][1], g_L[k][b][2], g_L[k][b][3]);
            g_tb[k][b][j] = S8j * q;
        }
    }
    __syncthreads();

    // ---- phase 4: final sums, one thread per output
    if (tid < 288) {
        const int b = tid / 18, i = tid % 18;
        float z;
        if (i == 8) {
            z = signed_dot(g_L[8][b][0], g_L[8][b][1], g_L[8][b][2], g_L[8][b][3],
                           g_S[8][b][0], g_S[8][b][1], g_S[8][b][2], g_S[8][b][3]);
        } else {
            const float* tp = (i < 8) ? &g_tb[i][b][0] : &g_tf[i - 9][b][0];
            z = ((tp[0] + tp[1]) + (tp[2] + tp[3]))
              + ((tp[4] + tp[5]) + (tp[6] + tp[7]));
        }
        out[b * NQ + i] = z;
    }
}

extern "C" void kernel_launch(void* const* d_in, const int* in_sizes, int n_in,
                              void* d_out, int out_size) {
    const float* in  = (const float*)d_in[0];
    float*       out = (float*)d_out;
    quantum_mps_kernel<<<1, 320>>>(in, out);
}

// round 8
// speedup vs baseline: 1.5140x; 1.5140x over previous
#include <cuda_runtime.h>
#include <cuda_bf16.h>

#define NQ    18
#define NBAT  16

typedef unsigned long long u64;

// ---- f32x2 packed helpers ----
__device__ __forceinline__ u64 pk(float lo, float hi) {
    u64 r; asm("mov.b64 %0,{%1,%2};" : "=l"(r) : "f"(lo), "f"(hi)); return r;
}
__device__ __forceinline__ void upk(u64 v, float& lo, float& hi) {
    asm("mov.b64 {%0,%1},%2;" : "=f"(lo), "=f"(hi) : "l"(v));
}
__device__ __forceinline__ u64 fma2(u64 a, u64 b, u64 c) {
    u64 d; asm("fma.rn.f32x2 %0,%1,%2,%3;" : "=l"(d) : "l"(a), "l"(b), "l"(c)); return d;
}
__device__ __forceinline__ u64 mul2(u64 a, u64 b) {
    u64 d; asm("mul.rn.f32x2 %0,%1,%2;" : "=l"(d) : "l"(a), "l"(b)); return d;
}
__device__ __forceinline__ u64 add2(u64 a, u64 b) {
    u64 d; asm("add.rn.f32x2 %0,%1,%2;" : "=l"(d) : "l"(a), "l"(b)); return d;
}

// Bond state s=(w<<2)|(y<<1)|y' packed as pairs P[p]=(2p,2p+1).
// Forward site op F = C*B*A; backward (transpose) G = B*A*C.
// Coeff layout per site: c[0]=(C0,S0), c[1]=r0_even, c[2]=r0_odd,
//                        c[3]=r1_even, c[4]=r1_odd   (verified R2-R6).

__device__ __forceinline__ void site_fwd(const u64* c, u64& P0, u64& P1, u64& P2, u64& P3) {
    const u64 r0e = c[1], r0o = c[2], r1e = c[3], r1o = c[4];
    float C0, S0; upk(c[0], C0, S0);
    const u64 C0p = pk(C0, C0), S0p = pk(S0, S0);
    const u64 T0 = fma2(C0p, P0, mul2(S0p, P1));
    const u64 T1 = fma2(C0p, P1, mul2(S0p, P0));
    const u64 T2 = fma2(C0p, P2, mul2(S0p, P3));
    const u64 T3 = fma2(C0p, P3, mul2(S0p, P2));
    float t0,t1,t2,t3,t4,t5,t6,t7;
    upk(T0,t0,t1); upk(T1,t2,t3); upk(T2,t4,t5); upk(T3,t6,t7);
    const u64 V0 = pk(fmaf(C0,t0,S0*t1), fmaf(C0,t1,S0*t0));
    const u64 V1 = pk(fmaf(C0,t2,S0*t3), fmaf(C0,t3,S0*t2));
    const u64 V2 = pk(fmaf(C0,t4,S0*t5), fmaf(C0,t5,S0*t4));
    const u64 V3 = pk(fmaf(C0,t6,S0*t7), fmaf(C0,t7,S0*t6));
    P0 = fma2(r0e, V0, mul2(r1e, V2));
    P1 = fma2(r0o, V1, mul2(r1o, V3));
    P2 = fma2(r0e, V2, mul2(r1e, V0));
    P3 = fma2(r0o, V3, mul2(r1o, V1));
}

__device__ __forceinline__ void site_bwd(const u64* c, u64& U0, u64& U1, u64& U2, u64& U3) {
    const u64 r0e = c[1], r0o = c[2], r1e = c[3], r1o = c[4];
    float C0, S0; upk(c[0], C0, S0);
    const u64 C0p = pk(C0, C0), S0p = pk(S0, S0);
    const u64 T0 = fma2(r0e, U0, mul2(r1e, U2));
    const u64 T1 = fma2(r0o, U1, mul2(r1o, U3));
    const u64 T2 = fma2(r0e, U2, mul2(r1e, U0));
    const u64 T3 = fma2(r0o, U3, mul2(r1o, U1));
    const u64 W0 = fma2(C0p, T0, mul2(S0p, T1));
    const u64 W1 = fma2(C0p, T1, mul2(S0p, T0));
    const u64 W2 = fma2(C0p, T2, mul2(S0p, T3));
    const u64 W3 = fma2(C0p, T3, mul2(S0p, T2));
    float w0,w1,w2,w3,w4,w5,w6,w7;
    upk(W0,w0,w1); upk(W1,w2,w3); upk(W2,w4,w5); upk(W3,w6,w7);
    U0 = pk(fmaf(C0,w0,S0*w1), fmaf(C0,w1,S0*w0));
    U1 = pk(fmaf(C0,w2,S0*w3), fmaf(C0,w3,S0*w2));
    U2 = pk(fmaf(C0,w4,S0*w5), fmaf(C0,w5,S0*w4));
    U3 = pk(fmaf(C0,w6,S0*w7), fmaf(C0,w7,S0*w6));
}

__global__ void __launch_bounds__(64, 1)
quantum_mps_kernel(const float* __restrict__ in, float* __restrict__ out) {
    __shared__ u64 cst[NQ][5];   // per-site packed coefficients (this block's batch)
    __shared__ u64 sL [NQ][4];   // forward prefix vectors L_0..L_17
    __shared__ u64 sS [NQ][4];   // backward suffix vectors S_0..S_17

    const int b   = blockIdx.x;        // one batch per block / per SM
    const int tid = threadIdx.x;

    // ---- phase 1: 18 threads, one site each: 2 sincosf + coefficient pack
    if (tid < NQ) {
        const float* ang = in + b * (2 * NQ);
        float c0, sn0, c1, sn1;
        __sincosf(0.5f * ang[tid],      &sn0, &c0);
        __sincosf(0.5f * ang[NQ + tid], &sn1, &c1);
        const float cc = c1 * c1, ss = sn1 * sn1, cs = c1 * sn1, ncs = -cs;
        cst[tid][0] = pk(c0,  sn0);
        cst[tid][1] = pk(cc,  ncs);   // r0, even pairs
        cst[tid][2] = pk(ncs, ss);    // r0, odd pairs
        cst[tid][3] = pk(ss,  cs);    // r1, even pairs
        cst[tid][4] = pk(cs,  cc);    // r1, odd pairs
    }
    __syncthreads();

    // ---- phase 2: two serial sweeps on two warps (lane 0 of each)
    if (tid == 0) {
        // forward: L_i = F_i L_{i-1}
        u64 P0 = pk(1.f, 0.f), P1 = pk(0.f, 0.f), P2 = P1, P3 = P1;
        #pragma unroll
        for (int i = 0; i < NQ; i++) {
            site_fwd(cst[i], P0, P1, P2, P3);
            sL[i][0] = P0; sL[i][1] = P1; sL[i][2] = P2; sL[i][3] = P3;
        }
    } else if (tid == 32) {
        // backward: S_17 = 1; S_{i-1} = G_i S_i
        u64 U0 = pk(1.f, 1.f), U1 = U0, U2 = U0, U3 = U0;
        sS[NQ - 1][0] = U0; sS[NQ - 1][1] = U1;
        sS[NQ - 1][2] = U2; sS[NQ - 1][3] = U3;
        #pragma unroll
        for (int i = NQ - 1; i >= 1; i--) {
            site_bwd(cst[i], U0, U1, U2, U3);
            sS[i - 1][0] = U0; sS[i - 1][1] = U1;
            sS[i - 1][2] = U2; sS[i - 1][3] = U3;
        }
    }
    __syncthreads();

    // ---- phase 3: readout, one thread per site
    // Z_i = sum_s (-1)^w L_i[s] S_i[s]  (sign pattern + + - - over the 4 pairs)
    if (tid < NQ) {
        const u64 Ap = add2(mul2(sL[tid][0], sS[tid][0]),
                            mul2(sL[tid][1], sS[tid][1]));
        const u64 An = add2(mul2(sL[tid][2], sS[tid][2]),
                            mul2(sL[tid][3], sS[tid][3]));
        float pl, ph, nl, nh;
        upk(Ap, pl, ph); upk(An, nl, nh);
        out[b * NQ + tid] = (pl + ph) - (nl + nh);
    }
}

extern "C" void kernel_launch(void* const* d_in, const int* in_sizes, int n_in,
                              void* d_out, int out_size) {
    const float* in  = (const float*)d_in[0];
    float*       out = (float*)d_out;
    quantum_mps_kernel<<<NBAT, 64>>>(in, out);
}

// round 9
// speedup vs baseline: 1.5652x; 1.0338x over previous
#include <cuda_runtime.h>
#include <cuda_bf16.h>

#define NQ    18
#define NBAT  16

typedef unsigned long long u64;

// ---- f32x2 packed helpers ----
__device__ __forceinline__ u64 pk(float lo, float hi) {
    u64 r; asm("mov.b64 %0,{%1,%2};" : "=l"(r) : "f"(lo), "f"(hi)); return r;
}
__device__ __forceinline__ void upk(u64 v, float& lo, float& hi) {
    asm("mov.b64 {%0,%1},%2;" : "=f"(lo), "=f"(hi) : "l"(v));
}
__device__ __forceinline__ u64 fma2(u64 a, u64 b, u64 c) {
    u64 d; asm("fma.rn.f32x2 %0,%1,%2,%3;" : "=l"(d) : "l"(a), "l"(b), "l"(c)); return d;
}
__device__ __forceinline__ u64 mul2(u64 a, u64 b) {
    u64 d; asm("mul.rn.f32x2 %0,%1,%2;" : "=l"(d) : "l"(a), "l"(b)); return d;
}
__device__ __forceinline__ u64 add2(u64 a, u64 b) {
    u64 d; asm("add.rn.f32x2 %0,%1,%2;" : "=l"(d) : "l"(a), "l"(b)); return d;
}
__device__ __forceinline__ u64 sub2(u64 a, u64 b) {
    u64 d; asm("sub.rn.f32x2 %0,%1,%2;" : "=l"(d) : "l"(a), "l"(b)); return d;
}
__device__ __forceinline__ u64 swap2(u64 v) {
    float lo, hi; upk(v, lo, hi); return pk(hi, lo);
}

// Symmetric-subspace bond: 6 states = w x class{00, 01(=10), 11}, packed as
// u64 pairs (w=0, w=1) per class. Effective site op (exact restriction of the
// verified 8-dim op; self-matching under transpose so bwd reuses the same
// stages in reverse order):
//   AB (layer-0, class mixing):  t = q00+q11 ; m = cs0*(2*q01)
//     v00 = cc0*q00 + ss0*q11 + m ; v01 = cs0*t + q01 ; v11 = ss0*q00 + cc0*q11 + m
//   C  (layer-1, w mixing):  p00 = cc1*v00 + ss1*sw(v00)
//     p01 = cs1*(sw(v01) - v01) ;  p11 = ss1*v11 + cc1*sw(v11)
// Readout: Z = lo-hi of [L00*S00 + 2*L01*S01 + L11*S11].

// per-site packed constants: 0=cc0p 1=ss0p 2=cs0p 3=cc1p 4=ss1p 5=cs1p
// pad to 7 u64 (14-word lane stride: conflict-free for 16 lanes)
__shared__ u64 g_cst[NQ][NBAT][7];
__shared__ u64 g_L[NQ][NBAT][5];   // L00,L01,L11 (+pad, 10-word stride)
__shared__ u64 g_S[NQ][NBAT][5];   // S00,S01,S11

struct St { u64 q00, q01, q11; };

__device__ __forceinline__ void stage_AB(const u64* c, St& x) {
    const u64 t  = add2(x.q00, x.q11);
    const u64 v01 = fma2(c[2], t, x.q01);
    const u64 m  = mul2(c[2], add2(x.q01, x.q01));
    const u64 v00 = fma2(c[0], x.q00, fma2(c[1], x.q11, m));
    const u64 v11 = fma2(c[1], x.q00, fma2(c[0], x.q11, m));
    x.q00 = v00; x.q01 = v01; x.q11 = v11;
}
__device__ __forceinline__ void stage_C(const u64* c, St& x) {
    const u64 p00 = fma2(c[3], x.q00, mul2(c[4], swap2(x.q00)));
    const u64 p01 = mul2(c[5], sub2(swap2(x.q01), x.q01));
    const u64 p11 = fma2(c[4], x.q11, mul2(c[3], swap2(x.q11)));
    x.q00 = p00; x.q01 = p01; x.q11 = p11;
}

__global__ void __launch_bounds__(128, 1)
quantum_mps_kernel(const float* __restrict__ in, float* __restrict__ out) {
    const int tid = threadIdx.x;
    const int wid = tid >> 5;
    const int b   = tid & 31;
    const bool active = (b < NBAT);

    // ---- phase 1: coefficients. t<96 -> 3 consecutive sites of one batch
    if (tid < 96) {
        const int pb = tid / 6;
        const int s0 = 3 * (tid % 6);
        const float* a0 = in + pb * (2 * NQ) + s0;
        const float* a1 = a0 + NQ;
        #pragma unroll
        for (int j = 0; j < 3; j++) {
            const int s = s0 + j;
            float c0, sn0, c1, sn1;
            __sincosf(0.5f * a0[j], &sn0, &c0);
            __sincosf(0.5f * a1[j], &sn1, &c1);
            g_cst[s][pb][0] = pk(c0 * c0,   c0 * c0);
            g_cst[s][pb][1] = pk(sn0 * sn0, sn0 * sn0);
            g_cst[s][pb][2] = pk(c0 * sn0,  c0 * sn0);
            g_cst[s][pb][3] = pk(c1 * c1,   c1 * c1);
            g_cst[s][pb][4] = pk(sn1 * sn1, sn1 * sn1);
            g_cst[s][pb][5] = pk(c1 * sn1,  c1 * sn1);
        }
    }
    __syncthreads();

    // ---- phase 2: warp 0 forward sweep, warp 1 backward sweep
    if (active && wid == 0) {
        St x; x.q00 = pk(1.f, 0.f); x.q01 = pk(0.f, 0.f); x.q11 = x.q01;
        #pragma unroll
        for (int i = 0; i < NQ; i++) {
            stage_AB(g_cst[i][b], x);
            stage_C (g_cst[i][b], x);
            g_L[i][b][0] = x.q00; g_L[i][b][1] = x.q01; g_L[i][b][2] = x.q11;
        }
    } else if (active && wid == 1) {
        St x; x.q00 = pk(1.f, 1.f); x.q01 = x.q00; x.q11 = x.q00;
        g_S[NQ-1][b][0] = x.q00; g_S[NQ-1][b][1] = x.q01; g_S[NQ-1][b][2] = x.q11;
        #pragma unroll
        for (int i = NQ - 1; i >= 1; i--) {
            stage_C (g_cst[i][b], x);   // transpose order: C then AB
            stage_AB(g_cst[i][b], x);
            g_S[i-1][b][0] = x.q00; g_S[i-1][b][1] = x.q01; g_S[i-1][b][2] = x.q11;
        }
    }
    __syncthreads();

    // ---- phase 3: readout split 5/5/4/4 across warps
    if (active) {
        const int st = (wid < 2) ? wid * 5 : 10 + (wid - 2) * 4;
        const int en = st + ((wid < 2) ? 5 : 4);
        #pragma unroll
        for (int i = st; i < en; i++) {
            const u64 M0 = mul2(g_L[i][b][0], g_S[i][b][0]);
            const u64 M1 = mul2(g_L[i][b][1], g_S[i][b][1]);
            const u64 M2 = mul2(g_L[i][b][2], g_S[i][b][2]);
            const u64 sum = add2(add2(M0, M2), add2(M1, M1));
            float lo, hi; upk(sum, lo, hi);
            out[b * NQ + i] = lo - hi;
        }
    }
}

extern "C" void kernel_launch(void* const* d_in, const int* in_sizes, int n_in,
                              void* d_out, int out_size) {
    const float* in  = (const float*)d_in[0];
    float*       out = (float*)d_out;
    quantum_mps_kernel<<<1, 128>>>(in, out);
}